// round 7
// baseline (speedup 1.0000x reference)
#include <cuda_runtime.h>
#include <math.h>

// ---------------------------------------------------------------------------
// ExpertChoiceRouter: scores = sigmoid(x@w) [N=16384, D=2048];
// K = floor(N*0.67); top-K -> 0/1 mask (stable ties: lowest index first);
// out[N] = -mean(top_scores)*1e-3.  current_mask all-True -> ignored.
//
// K1 (2048 CTAs): GEMV -> key/score/8192-bin hist; LAST CTA finds threshold
//     bin B + in-bin rank kr, zeroes hist (fence+done-counter pattern).
// K2 (64 CTAs): mask write + partial score sums + bin-B candidate collect;
//     LAST block does exact stable in-bin selection + aux loss.
// ---------------------------------------------------------------------------

#define MAX_N   32768
#define NBINS   8192
#define BSHIFT  19            // bin = key >> 19 (13-bit prefix)
#define CANDS   4096

__device__ unsigned int g_key[MAX_N];
__device__ float        g_score[MAX_N];
__device__ unsigned int g_hist[NBINS];     // zero at load; K1 tail re-zeroes
__device__ unsigned int g_selB;
__device__ int          g_selKr;
__device__ unsigned int g_ccount;          // zero at load; K2 tail resets
__device__ unsigned int g_cand_key[MAX_N];
__device__ int          g_cand_idx[MAX_N];
__device__ float        g_psum[1024];
__device__ unsigned int g_done1;           // zero at load; self-resetting
__device__ unsigned int g_done2;

__device__ __forceinline__ unsigned int f2key(float f) {
    unsigned int u = __float_as_uint(f);
    return (u & 0x80000000u) ? ~u : (u | 0x80000000u);
}

// ---------------------------------------------------------------------------
// K1: GEMV (one warp per row) + fused threshold-bin finder in the last CTA.
// ---------------------------------------------------------------------------
__global__ void __launch_bounds__(256)
router_gemv_kernel(const float* __restrict__ x,
                   const float* __restrict__ w,
                   int N, int D, int K) {
    __shared__ int s_last;
    __shared__ unsigned int s_wt[8];
    __shared__ unsigned int s_wb[8];
    __shared__ unsigned int s_tot;

    const int tid  = threadIdx.x;
    const int lane = tid & 31;
    const int wid  = tid >> 5;
    const int gwarp = blockIdx.x * 8 + wid;

    if (gwarp < N) {
        const float4* __restrict__ xr =
            reinterpret_cast<const float4*>(x + (size_t)gwarp * D);
        const float4* __restrict__ wv = reinterpret_cast<const float4*>(w);
        const int nv = D >> 2;

        float acc = 0.f;
        #pragma unroll 8
        for (int i = lane; i < nv; i += 32) {
            float4 a = __ldcs(&xr[i]);
            float4 b = __ldg(&wv[i]);
            acc += a.x * b.x + a.y * b.y + a.z * b.z + a.w * b.w;
        }
        #pragma unroll
        for (int o = 16; o > 0; o >>= 1)
            acc += __shfl_down_sync(0xFFFFFFFFu, acc, o);

        if (lane == 0) {
            unsigned int key = f2key(acc);
            g_key[gwarp]   = key;
            g_score[gwarp] = 1.0f / (1.0f + __expf(-acc));
            atomicAdd(&g_hist[key >> BSHIFT], 1u);
        }
    }

    // ---- done-counter: last CTA finds the threshold bin ----
    __threadfence();
    __syncthreads();
    if (tid == 0)
        s_last = (atomicAdd(&g_done1, 1u) == gridDim.x - 1) ? 1 : 0;
    __syncthreads();
    if (!s_last) return;

    if (tid == 0) g_done1 = 0;   // reset for next graph replay

    // 256 threads x 32 bins each
    const unsigned int hbase = (unsigned)tid * 32u;
    unsigned int hv[32];
    unsigned int st = 0;
    #pragma unroll
    for (int j = 0; j < 8; j++) {
        uint4 v = __ldcg(reinterpret_cast<const uint4*>(&g_hist[hbase + j * 4]));
        hv[j*4+0] = v.x; hv[j*4+1] = v.y; hv[j*4+2] = v.z; hv[j*4+3] = v.w;
        st += v.x + v.y + v.z + v.w;
    }
    // CTA prefix scan of per-thread totals (8 warps)
    unsigned int inc = st;
    #pragma unroll
    for (int o = 1; o < 32; o <<= 1) {
        unsigned int v = __shfl_up_sync(0xFFFFFFFFu, inc, o);
        if (lane >= o) inc += v;
    }
    if (lane == 31) s_wt[wid] = inc;
    __syncthreads();
    if (tid == 0) {
        unsigned int base = 0;
        #pragma unroll
        for (int j = 0; j < 8; j++) { s_wb[j] = base; base += s_wt[j]; }
        s_tot = base;
    }
    __syncthreads();
    const unsigned int pfx = s_wb[wid] + (inc - st);
    const unsigned int suf = s_tot - pfx - st;   // count in bins above mine

    if (suf < (unsigned)K && suf + st >= (unsigned)K) {
        unsigned int Snext = suf;
        #pragma unroll
        for (int j = 31; j >= 0; j--) {
            unsigned int Sb = Snext + hv[j];
            if (Sb >= (unsigned)K && Snext < (unsigned)K) {
                g_selB  = hbase + (unsigned)j;
                g_selKr = K - (int)Snext;
            }
            Snext = Sb;
        }
    }
    // zero own bins for next replay
    uint4 z = make_uint4(0u, 0u, 0u, 0u);
    #pragma unroll
    for (int j = 0; j < 8; j++)
        *reinterpret_cast<uint4*>(&g_hist[hbase + j * 4]) = z;
}

// ---------------------------------------------------------------------------
// K2: mask write + partial sums + candidates; last block finalizes.
// ---------------------------------------------------------------------------
#define K2_THREADS 64

__global__ void __launch_bounds__(K2_THREADS)
router_mask_final_kernel(float* __restrict__ out, int N, int K, int out_size) {
    __shared__ float        s_w[K2_THREADS / 32];
    __shared__ int          s_last;
    __shared__ unsigned int sk[CANDS];
    __shared__ int          si[CANDS];
    __shared__ double       sd[K2_THREADS];

    const int tid  = threadIdx.x;
    const int lane = tid & 31;
    const int wid  = tid >> 5;
    const unsigned int B = g_selB;
    const int i = (blockIdx.x * K2_THREADS + tid) * 4;

    float sum = 0.0f;
    if (i + 3 < N) {
        uint4  kv = *reinterpret_cast<const uint4*>(&g_key[i]);
        float4 sv = *reinterpret_cast<const float4*>(&g_score[i]);
        const unsigned int ka[4] = {kv.x, kv.y, kv.z, kv.w};
        const float        sa[4] = {sv.x, sv.y, sv.z, sv.w};
        float4 mv;
        float* mp = &mv.x;
        #pragma unroll
        for (int j = 0; j < 4; j++) {
            unsigned int bin = ka[j] >> BSHIFT;
            float m = 0.0f;
            if (bin > B) { m = 1.0f; sum += sa[j]; }
            else if (bin == B) {
                unsigned int p = atomicAdd(&g_ccount, 1u);
                if (p < MAX_N) { g_cand_key[p] = ka[j]; g_cand_idx[p] = i + j; }
            }
            mp[j] = m;
        }
        *reinterpret_cast<float4*>(&out[i]) = mv;
    }

    // block partial sum -> g_psum[blockIdx.x]
    #pragma unroll
    for (int o = 16; o > 0; o >>= 1)
        sum += __shfl_down_sync(0xFFFFFFFFu, sum, o);
    if (lane == 0) s_w[wid] = sum;
    __syncthreads();
    if (tid == 0) {
        float t = 0.0f;
        #pragma unroll
        for (int j = 0; j < K2_THREADS / 32; j++) t += s_w[j];
        g_psum[blockIdx.x] = t;
    }

    // ---- done-counter: last block finalizes ----
    __threadfence();
    __syncthreads();
    if (tid == 0)
        s_last = (atomicAdd(&g_done2, 1u) == gridDim.x - 1) ? 1 : 0;
    __syncthreads();
    if (!s_last) return;

    int m = (int)__ldcg(&g_ccount);
    if (m > MAX_N) m = MAX_N;
    const int kr = g_selKr;
    const bool fit = (m <= CANDS);

    if (fit) {
        for (int c = tid; c < m; c += K2_THREADS) {
            sk[c] = __ldcg(&g_cand_key[c]);
            si[c] = __ldcg(&g_cand_idx[c]);
        }
    }
    __syncthreads();

    double loc = 0.0;
    if (fit) {
        for (int c = tid; c < m; c += K2_THREADS) {
            unsigned int kc = sk[c];
            int          ic = si[c];
            int rank = 0;
            for (int j = 0; j < m; j++) {
                unsigned int kj = sk[j];
                if (kj > kc) rank++;
                else if (kj == kc) rank += (si[j] < ic);
            }
            if (rank < kr) {                       // stable top-kr of bin B
                out[ic] = 1.0f;
                loc += (double)__ldcg(&g_score[ic]);
            }
        }
    } else {                                        // ultra-rare fallback
        for (int c = tid; c < m; c += K2_THREADS) {
            unsigned int kc = __ldcg(&g_cand_key[c]);
            int          ic = __ldcg(&g_cand_idx[c]);
            int rank = 0;
            for (int j = 0; j < m; j++) {
                unsigned int kj = __ldcg(&g_cand_key[j]);
                if (kj > kc) rank++;
                else if (kj == kc) rank += (__ldcg(&g_cand_idx[j]) < ic);
            }
            if (rank < kr) {
                out[ic] = 1.0f;
                loc += (double)__ldcg(&g_score[ic]);
            }
        }
    }
    for (int j = tid; j < (int)gridDim.x; j += K2_THREADS)
        loc += (double)__ldcg(&g_psum[j]);

    sd[tid] = loc;
    __syncthreads();
    #pragma unroll
    for (int s = K2_THREADS / 2; s > 0; s >>= 1) {
        if (tid < s) sd[tid] += sd[tid + s];
        __syncthreads();
    }
    if (tid == 0) {
        if (out_size > N)
            out[N] = (float)(-(sd[0] / (double)K) * 0.001);
        g_ccount = 0;      // reset for next graph replay
        g_done2  = 0;
    }
}

// ---------------------------------------------------------------------------
extern "C" void kernel_launch(void* const* d_in, const int* in_sizes, int n_in,
                              void* d_out, int out_size) {
    const float* x = (const float*)d_in[0];
    const float* w = (const float*)d_in[2];
    float* out = (float*)d_out;

    const int N = in_sizes[1];
    const int D = in_sizes[2];
    int K = (int)((double)N * 0.67);
    if (K < 1) K = 1;

    const int b1 = (N + 7) / 8;                          // 8 row-warps / CTA
    const int b2 = (N + K2_THREADS * 4 - 1) / (K2_THREADS * 4);
    router_gemv_kernel<<<b1, 256>>>(x, w, N, D, K);
    router_mask_final_kernel<<<b2, K2_THREADS>>>(out, N, K, out_size);
}

// round 8
// speedup vs baseline: 1.1953x; 1.1953x over previous
#include <cuda_runtime.h>
#include <math.h>

// ---------------------------------------------------------------------------
// ExpertChoiceRouter: scores = sigmoid(x@w) [N=16384, D=2048];
// K = floor(N*0.67); top-K -> 0/1 mask (stable ties: lowest index first);
// out[N] = -mean(top_scores)*1e-3.  current_mask all-True -> ignored.
//
// K1 (2048 CTAs): GEMV -> key, sigmoid score, 8192-bin histogram.
// K2 (32 CTAs):  each block independently scans the hist -> threshold bin B;
//                mask write + partial score sums + bin-B candidate collect.
// K3 (1 CTA, 1024 thr): re-derives B,kr from hist, zeroes hist, exact stable
//                rank among candidates, aux loss, resets counters.
// No fences, no done-counters, no cross-kernel scalar handoffs.
// ---------------------------------------------------------------------------

#define MAX_N   32768
#define NBINS   8192
#define BSHIFT  19            // bin = key >> 19 (13-bit prefix)
#define CANDS   4096

__device__ unsigned int g_key[MAX_N];
__device__ float        g_score[MAX_N];
__device__ unsigned int g_hist[NBINS];     // zero at load; K3 re-zeroes
__device__ unsigned int g_ccount;          // zero at load; K3 resets
__device__ unsigned int g_cand_key[MAX_N];
__device__ int          g_cand_idx[MAX_N];
__device__ float        g_psum[256];

__device__ __forceinline__ unsigned int f2key(float f) {
    unsigned int u = __float_as_uint(f);
    return (u & 0x80000000u) ? ~u : (u | 0x80000000u);
}

// ---------------------------------------------------------------------------
// Block-wide threshold finder: scans g_hist, returns bin B of the K-th
// largest key and kr = how many to take from bin B. Deterministic.
// s_wt: [blockDim/32] words; s_res: [3] words.
// ---------------------------------------------------------------------------
__device__ __forceinline__ void find_threshold(int K, unsigned int* retB, int* retKr,
                                               unsigned int* s_wt, unsigned int* s_res) {
    const int tid  = threadIdx.x;
    const int lane = tid & 31;
    const int wid  = tid >> 5;
    const int nw   = blockDim.x >> 5;
    const int bper = NBINS / blockDim.x;
    const unsigned int hbase = (unsigned)tid * bper;

    unsigned int st = 0;
    for (int j = 0; j < bper; j += 4) {
        uint4 v = *reinterpret_cast<const uint4*>(&g_hist[hbase + j]);
        st += v.x + v.y + v.z + v.w;
    }
    unsigned int inc = st;
    #pragma unroll
    for (int o = 1; o < 32; o <<= 1) {
        unsigned int v = __shfl_up_sync(0xFFFFFFFFu, inc, o);
        if (lane >= o) inc += v;
    }
    if (lane == 31) s_wt[wid] = inc;
    __syncthreads();
    if (tid == 0) {
        unsigned int b = 0;
        for (int j = 0; j < nw; j++) { unsigned int t = s_wt[j]; s_wt[j] = b; b += t; }
        s_res[2] = b;
    }
    __syncthreads();
    const unsigned int tot = s_res[2];
    const unsigned int pfx = s_wt[wid] + (inc - st);
    const unsigned int suf = tot - pfx - st;     // keys in bins above mine

    if (suf < (unsigned)K && suf + st >= (unsigned)K) {
        unsigned int Snext = suf;
        for (int j = bper - 1; j >= 0; j--) {    // owner re-walks its bins (L1-hot)
            unsigned int h  = g_hist[hbase + j];
            unsigned int Sb = Snext + h;
            if (Sb >= (unsigned)K && Snext < (unsigned)K) {
                s_res[0] = hbase + (unsigned)j;
                s_res[1] = (unsigned)(K - (int)Snext);
            }
            Snext = Sb;
        }
    }
    __syncthreads();
    *retB  = s_res[0];
    *retKr = (int)s_res[1];
}

// ---------------------------------------------------------------------------
// K1: GEMV, one warp per row. Streaming x, L1-resident w. HBM-bound (128MB).
// ---------------------------------------------------------------------------
__global__ void __launch_bounds__(256)
router_gemv_kernel(const float* __restrict__ x,
                   const float* __restrict__ w,
                   int N, int D) {
    int gwarp = (blockIdx.x * blockDim.x + threadIdx.x) >> 5;
    int lane  = threadIdx.x & 31;
    if (gwarp >= N) return;

    const float4* __restrict__ xr = reinterpret_cast<const float4*>(x + (size_t)gwarp * D);
    const float4* __restrict__ wv = reinterpret_cast<const float4*>(w);
    const int nv = D >> 2;

    float acc = 0.f;
    #pragma unroll 8
    for (int i = lane; i < nv; i += 32) {
        float4 a = __ldcs(&xr[i]);
        float4 b = __ldg(&wv[i]);
        acc += a.x * b.x + a.y * b.y + a.z * b.z + a.w * b.w;
    }
    #pragma unroll
    for (int o = 16; o > 0; o >>= 1)
        acc += __shfl_down_sync(0xFFFFFFFFu, acc, o);

    if (lane == 0) {
        unsigned int key = f2key(acc);
        g_key[gwarp]   = key;
        g_score[gwarp] = 1.0f / (1.0f + __expf(-acc));
        atomicAdd(&g_hist[key >> BSHIFT], 1u);
    }
}

// ---------------------------------------------------------------------------
// K2: per-block redundant threshold scan + mask write + psum + candidates.
// ---------------------------------------------------------------------------
#define K2_THREADS 128

__global__ void __launch_bounds__(K2_THREADS)
router_mask_kernel(float* __restrict__ out, int N, int K) {
    __shared__ unsigned int s_wt[K2_THREADS / 32];
    __shared__ unsigned int s_res[3];
    __shared__ float        s_w[K2_THREADS / 32];

    unsigned int B; int kr;
    find_threshold(K, &B, &kr, s_wt, s_res);

    const int tid = threadIdx.x;
    const int i   = (blockIdx.x * K2_THREADS + tid) * 4;

    float sum = 0.0f;
    if (i + 3 < N) {
        uint4  kv = *reinterpret_cast<const uint4*>(&g_key[i]);
        float4 sv = *reinterpret_cast<const float4*>(&g_score[i]);
        const unsigned int ka[4] = {kv.x, kv.y, kv.z, kv.w};
        const float        sa[4] = {sv.x, sv.y, sv.z, sv.w};
        float4 mv;
        float* mp = &mv.x;
        #pragma unroll
        for (int j = 0; j < 4; j++) {
            unsigned int bin = ka[j] >> BSHIFT;
            float m = 0.0f;
            if (bin > B) { m = 1.0f; sum += sa[j]; }
            else if (bin == B) {
                unsigned int p = atomicAdd(&g_ccount, 1u);
                if (p < MAX_N) { g_cand_key[p] = ka[j]; g_cand_idx[p] = i + j; }
            }
            mp[j] = m;
        }
        *reinterpret_cast<float4*>(&out[i]) = mv;
    } else {
        for (int j = 0; j < 4; j++) {
            int idx = i + j;
            if (idx < N) {
                unsigned int k = g_key[idx];
                unsigned int bin = k >> BSHIFT;
                float m = 0.0f;
                if (bin > B) { m = 1.0f; sum += g_score[idx]; }
                else if (bin == B) {
                    unsigned int p = atomicAdd(&g_ccount, 1u);
                    if (p < MAX_N) { g_cand_key[p] = k; g_cand_idx[p] = idx; }
                }
                out[idx] = m;
            }
        }
    }

    // block partial sum (fixed block->slot mapping: deterministic)
    const int lane = tid & 31;
    const int wid  = tid >> 5;
    #pragma unroll
    for (int o = 16; o > 0; o >>= 1)
        sum += __shfl_down_sync(0xFFFFFFFFu, sum, o);
    if (lane == 0) s_w[wid] = sum;
    __syncthreads();
    if (tid == 0) {
        float t = 0.0f;
        #pragma unroll
        for (int j = 0; j < K2_THREADS / 32; j++) t += s_w[j];
        g_psum[blockIdx.x] = t;
    }
}

// ---------------------------------------------------------------------------
// K3: finalize. Re-derives B,kr itself (no scalar handoff), zeroes hist,
// exact stable in-bin selection, aux loss, counter reset.
// ---------------------------------------------------------------------------
__global__ void __launch_bounds__(1024)
router_final_kernel(float* __restrict__ out, int N, int K, int out_size,
                    int nblocks2) {
    __shared__ unsigned int s_wt[32];
    __shared__ unsigned int s_res[3];
    __shared__ unsigned int sk[CANDS];
    __shared__ int          si[CANDS];
    __shared__ double       s_d[32];

    const int tid  = threadIdx.x;
    const int lane = tid & 31;
    const int wid  = tid >> 5;

    unsigned int B; int kr;
    find_threshold(K, &B, &kr, s_wt, s_res);
    (void)B;

    // zero hist for next graph replay (8 bins / thread)
    {
        uint4 z = make_uint4(0u, 0u, 0u, 0u);
        uint4* hz = reinterpret_cast<uint4*>(&g_hist[tid * 8]);
        hz[0] = z; hz[1] = z;
    }

    int m = (int)g_ccount;
    if (m > MAX_N) m = MAX_N;
    const bool fit = (m <= CANDS);

    if (fit) {
        for (int c = tid; c < m; c += 1024) {
            sk[c] = g_cand_key[c];
            si[c] = g_cand_idx[c];
        }
    }
    __syncthreads();

    double loc = 0.0;
    if (fit) {
        for (int c = tid; c < m; c += 1024) {
            unsigned int kc = sk[c];
            int          ic = si[c];
            int rank = 0;
            for (int j = 0; j < m; j++) {
                unsigned int kj = sk[j];
                if (kj > kc) rank++;
                else if (kj == kc) rank += (si[j] < ic);
            }
            if (rank < kr) {                     // stable top-kr of bin B
                out[ic] = 1.0f;
                loc += (double)g_score[ic];
            }
        }
    } else {                                      // ultra-rare fallback
        for (int c = tid; c < m; c += 1024) {
            unsigned int kc = g_cand_key[c];
            int          ic = g_cand_idx[c];
            int rank = 0;
            for (int j = 0; j < m; j++) {
                unsigned int kj = g_cand_key[j];
                if (kj > kc) rank++;
                else if (kj == kc) rank += (g_cand_idx[j] < ic);
            }
            if (rank < kr) {
                out[ic] = 1.0f;
                loc += (double)g_score[ic];
            }
        }
    }
    if (tid < nblocks2) loc += (double)g_psum[tid];

    // f64 reduction: warp shuffles + one cross-warp step
    #pragma unroll
    for (int o = 16; o > 0; o >>= 1)
        loc += __shfl_down_sync(0xFFFFFFFFu, loc, o);
    if (lane == 0) s_d[wid] = loc;
    __syncthreads();
    if (wid == 0) {
        double v = s_d[lane];
        #pragma unroll
        for (int o = 16; o > 0; o >>= 1)
            v += __shfl_down_sync(0xFFFFFFFFu, v, o);
        if (lane == 0) {
            if (out_size > N)
                out[N] = (float)(-(v / (double)K) * 0.001);
            g_ccount = 0;          // reset for next graph replay
        }
    }
}

// ---------------------------------------------------------------------------
extern "C" void kernel_launch(void* const* d_in, const int* in_sizes, int n_in,
                              void* d_out, int out_size) {
    const float* x = (const float*)d_in[0];
    const float* w = (const float*)d_in[2];
    float* out = (float*)d_out;

    const int N = in_sizes[1];
    const int D = in_sizes[2];
    int K = (int)((double)N * 0.67);
    if (K < 1) K = 1;

    const int b1 = (N + 7) / 8;                              // 8 row-warps/CTA
    const int b2 = (N + K2_THREADS * 4 - 1) / (K2_THREADS * 4);
    router_gemv_kernel<<<b1, 256>>>(x, w, N, D);
    router_mask_kernel<<<b2, K2_THREADS>>>(out, N, K);
    router_final_kernel<<<1, 1024>>>(out, N, K, out_size, b2);
}